// round 2
// baseline (speedup 1.0000x reference)
#include <cuda_runtime.h>
#include <cstdint>

typedef unsigned long long ull;

#define BB 2048
#define SS 512
#define NROW (BB * SS)
#define G3 96
#define HID 32
#define INSZ 64

// -------- device scratch --------
__device__ float g_gx[(size_t)NROW * G3];   // precomputed input-part gates (+b_ih)
__device__ ull   g_Gp[16 * 32];             // packed pairs of G[i][j] = sum_k Wkey[k][i]*Wq[k][j]
__device__ float g_d[32];                   // d[j] = sum_k b_key[k]*Wq[k][j]
__device__ float g_gv[32];                  // g[i] = sum_k Wkey[k][i]*b_query[k]
__device__ float g_f[1];                    // f = b_key . b_query
__device__ float g_H[32 * 2];               // H[i][r] = sum_v Wval[v][i]*Wrec[r][v]
__device__ float g_e[2];                    // e[r] = sum_v b_value[v]*Wrec[r][v]

// -------- helpers --------
__device__ __forceinline__ void ffma2(ull& d, ull a, ull b) {
    asm("fma.rn.f32x2 %0, %1, %2, %0;" : "+l"(d) : "l"(a), "l"(b));
}
__device__ __forceinline__ ull pack2(float a, float b) {
    ull r; asm("mov.b64 %0, {%1, %2};" : "=l"(r) : "f"(a), "f"(b)); return r;
}
__device__ __forceinline__ float hsum(ull v) {
    return __uint_as_float((unsigned)v) + __uint_as_float((unsigned)(v >> 32));
}
__device__ __forceinline__ float wsum(float v) {
#pragma unroll
    for (int o = 16; o; o >>= 1) v += __shfl_xor_sync(0xffffffffu, v, o);
    return v;
}
__device__ __forceinline__ float sigmoidf_(float x) {
    return __fdividef(1.f, 1.f + __expf(-x));
}
__device__ __forceinline__ float tanhf_(float x) {
    return 1.f - __fdividef(2.f, __expf(2.f * x) + 1.f);
}

// ============================================================================
// Phase 0: precompute folded memory matrices
// ============================================================================
__global__ void precompute_kernel(
    const float* __restrict__ Wk, const float* __restrict__ bk,
    const float* __restrict__ Wq, const float* __restrict__ bq,
    const float* __restrict__ Wv, const float* __restrict__ bv,
    const float* __restrict__ Wr)
{
    __shared__ float Gs[32 * 32];
    int tid = threadIdx.x;
    {   // G[i][j]
        int i = tid >> 5, j = tid & 31;
        float s = 0.f;
        for (int k = 0; k < 64; ++k) s += Wk[k * 32 + i] * Wq[k * 32 + j];
        Gs[i * 32 + j] = s;
    }
    if (tid < 32) {
        float dv = 0.f, gv = 0.f;
        for (int k = 0; k < 64; ++k) {
            dv += bk[k] * Wq[k * 32 + tid];
            gv += Wk[k * 32 + tid] * bq[k];
        }
        g_d[tid] = dv; g_gv[tid] = gv;
    }
    if (tid == 0) {
        float f = 0.f;
        for (int k = 0; k < 64; ++k) f += bk[k] * bq[k];
        g_f[0] = f;
    }
    if (tid < 64) {
        int i = tid >> 1, r = tid & 1;
        float s = 0.f;
        for (int v = 0; v < 64; ++v) s += Wv[v * 32 + i] * Wr[r * 64 + v];
        g_H[i * 2 + r] = s;
    }
    if (tid < 2) {
        float s = 0.f;
        for (int v = 0; v < 64; ++v) s += bv[v] * Wr[tid * 64 + v];
        g_e[tid] = s;
    }
    __syncthreads();
    if (tid < 512) {
        int k = tid >> 5, j = tid & 31;
        g_Gp[tid] = pack2(Gs[(2 * k) * 32 + j], Gs[(2 * k + 1) * 32 + j]);
    }
}

// ============================================================================
// Phase 1: GX[row][96] = inputs[row][0:64] @ w_ih[:, :64].T + b_ih
// 128 threads/block, 256 rows/block, grid 4096.
// ============================================================================
__global__ __launch_bounds__(128) void phase1_kernel(
    const float* __restrict__ xin,
    const float* __restrict__ w_ih,
    const float* __restrict__ b_ih)
{
    __shared__ __align__(16) ulonglong2 w4s[16 * 96];   // [kq][j], 24 KB
    __shared__ __align__(16) ulonglong2 xb[4][128];     // per warp: 8 rows x 16 quads

    const int tid = threadIdx.x;
    const int w = tid >> 5, lane = tid & 31;

    for (int idx = tid; idx < 16 * 96; idx += 128) {
        int kq = idx / 96, j = idx % 96;
        const float* p = w_ih + j * 66 + kq * 4;
        ulonglong2 v; v.x = pack2(p[0], p[1]); v.y = pack2(p[2], p[3]);
        w4s[idx] = v;
    }
    const float b0 = b_ih[lane], b1 = b_ih[lane + 32], b2 = b_ih[lane + 64];
    __syncthreads();

    const int blockRow0 = blockIdx.x * 256;
    for (int tile = 0; tile < 8; ++tile) {
        const int rowBase = blockRow0 + tile * 32 + w * 8;
        const ulonglong2* src = (const ulonglong2*)(xin + (size_t)rowBase * INSZ);
        __syncwarp();
#pragma unroll
        for (int i = 0; i < 4; ++i) xb[w][lane + 32 * i] = src[lane + 32 * i];
        __syncwarp();

        ull acc[8][3];
#pragma unroll
        for (int r = 0; r < 8; ++r) { acc[r][0] = 0; acc[r][1] = 0; acc[r][2] = 0; }

#pragma unroll
        for (int kq = 0; kq < 16; ++kq) {
            ulonglong2 w0 = w4s[kq * 96 + lane];
            ulonglong2 w1 = w4s[kq * 96 + lane + 32];
            ulonglong2 w2 = w4s[kq * 96 + lane + 64];
#pragma unroll
            for (int r = 0; r < 8; ++r) {
                ulonglong2 xv = xb[w][r * 16 + kq];
                ffma2(acc[r][0], xv.x, w0.x); ffma2(acc[r][0], xv.y, w0.y);
                ffma2(acc[r][1], xv.x, w1.x); ffma2(acc[r][1], xv.y, w1.y);
                ffma2(acc[r][2], xv.x, w2.x); ffma2(acc[r][2], xv.y, w2.y);
            }
        }
#pragma unroll
        for (int r = 0; r < 8; ++r) {
            float* o = g_gx + (size_t)(rowBase + r) * G3;
            o[lane]      = hsum(acc[r][0]) + b0;
            o[lane + 32] = hsum(acc[r][1]) + b1;
            o[lane + 64] = hsum(acc[r][2]) + b2;
        }
    }
}

// ============================================================================
// Phase 2: sequential scan. One warp per batch element, lane = hidden index.
// 64 threads/block (2 warps), grid 1024 -> single wave at 14 warps/SM.
// ============================================================================
__global__ __launch_bounds__(64, 7) void phase2_kernel(
    const float* __restrict__ w_ih,
    const float* __restrict__ w_hh,
    const float* __restrict__ b_hh,
    const float* __restrict__ b_recall,
    float* __restrict__ hid)
{
    __shared__ __align__(16) float hbuf[2][32];
    __shared__ __align__(16) float hbuf2[2][32];

    const int tid = threadIdx.x;
    const int w = tid >> 5, lane = tid & 31;
    const int b = blockIdx.x * 2 + w;

    ull whh0[16], whh1[16], whh2[16];
    {
        const ulonglong2* p0 = (const ulonglong2*)(w_hh + (size_t)lane * 32);
        const ulonglong2* p1 = (const ulonglong2*)(w_hh + (size_t)(lane + 32) * 32);
        const ulonglong2* p2 = (const ulonglong2*)(w_hh + (size_t)(lane + 64) * 32);
#pragma unroll
        for (int i = 0; i < 8; ++i) {
            ulonglong2 v;
            v = p0[i]; whh0[2 * i] = v.x; whh0[2 * i + 1] = v.y;
            v = p1[i]; whh1[2 * i] = v.x; whh1[2 * i + 1] = v.y;
            v = p2[i]; whh2[2 * i] = v.x; whh2[2 * i + 1] = v.y;
        }
    }
    const float wr00 = w_ih[lane * 66 + 64],        wr01 = w_ih[lane * 66 + 65];
    const float wr10 = w_ih[(lane + 32) * 66 + 64], wr11 = w_ih[(lane + 32) * 66 + 65];
    const float wr20 = w_ih[(lane + 64) * 66 + 64], wr21 = w_ih[(lane + 64) * 66 + 65];
    const float bh0 = b_hh[lane], bh1 = b_hh[lane + 32], bh2 = b_hh[lane + 64];
    const float g_own = g_gv[lane], H0o = g_H[lane * 2], H1o = g_H[lane * 2 + 1];
    const float dj = g_d[lane], fv = g_f[0], e0c = g_e[0], e1c = g_e[1];
    const float br0 = b_recall[0], br1 = b_recall[1];

    float A0o = 0.f, A1o = 0.f, A2o = 0.f;
    float c0 = 0.f, c1 = 0.f, c2 = 0.f;
    float R00 = 0.f, R01 = 0.f, R10 = 0.f, R11 = 0.f, R20 = 0.f, R21 = 0.f;
    float retr0 = 0.f, retr1 = 0.f, h_own = 0.f;

    const float* gxp = g_gx + (size_t)b * SS * G3;
    float* hrow = hid + (size_t)b * SS * HID + lane;
    float gx0 = __ldg(gxp + lane), gx1 = __ldg(gxp + lane + 32), gx2 = __ldg(gxp + lane + 64);

    ull* hbU  = (ull*)hbuf[w];
    ull* hb2U = (ull*)hbuf2[w];

    for (int t = 0; t < SS; ++t) {
        // prefetch next step's gx
        const float* q = gxp + (size_t)((t + 1 < SS) ? t + 1 : t) * G3;
        float ngx0 = __ldg(q + lane), ngx1 = __ldg(q + lane + 32), ngx2 = __ldg(q + lane + 64);

        float gxr = fmaf(retr1, wr01, fmaf(retr0, wr00, gx0));
        float gxz = fmaf(retr1, wr11, fmaf(retr0, wr10, gx1));
        float gxn = fmaf(retr1, wr21, fmaf(retr0, wr20, gx2));

        hbuf[w][lane] = h_own;
        __syncwarp();
        ull ar = 0, az = 0, an = 0;
#pragma unroll
        for (int k = 0; k < 16; ++k) {
            ull hp = hbU[k];
            ffma2(ar, hp, whh0[k]);
            ffma2(az, hp, whh1[k]);
            ffma2(an, hp, whh2[k]);
        }
        __syncwarp();
        float ghr = hsum(ar) + bh0, ghz = hsum(az) + bh1, ghn = hsum(an) + bh2;

        float r = sigmoidf_(gxr + ghr);
        float z = sigmoidf_(gxz + ghz);
        float n = tanhf_(fmaf(r, ghn, gxn));
        float h_new = fmaf(z, h_own - n, n);     // (1-z)*n + z*h
        if (t == 3) h_new = 0.f;

        if (t < 3) {                              // memory write (folded)
            hbuf2[w][lane] = h_new;
            __syncwarp();
            ull aa = 0;
#pragma unroll
            for (int k = 0; k < 16; ++k) { ull hp = hb2U[k]; ffma2(aa, hp, g_Gp[k * 32 + lane]); }
            __syncwarp();
            float Av  = hsum(aa) + dj;
            float cv  = wsum(h_new * g_own) + fv;
            float Rv0 = wsum(h_new * H0o) + e0c;
            float Rv1 = wsum(h_new * H1o) + e1c;
            if (t == 0)      { A0o = Av; c0 = cv; R00 = Rv0; R01 = Rv1; }
            else if (t == 1) { A1o = Av; c1 = cv; R10 = Rv0; R11 = Rv1; }
            else             { A2o = Av; c2 = cv; R20 = Rv0; R21 = Rv1; }
        }

        // memory read (folded attention)
        float s0 = wsum(h_new * A0o) + c0;
        float s1 = wsum(h_new * A1o) + c1;
        float s2 = wsum(h_new * A2o) + c2;
        int counter = (t < 3) ? t : 3;
        float m0 = (0 < counter) ? s0 : -1e30f;
        float m1 = (1 < counter) ? s1 : -1e30f;
        float m2 = (2 < counter) ? s2 : -1e30f;
        float p0 = __expf(m0), p1 = __expf(m1), p2 = __expf(m2);
        float inv = __fdividef(1.f, p0 + p1 + p2);
        float nr0 = fmaf(p2, R20, fmaf(p1, R10, p0 * R00)) * inv + br0;
        float nr1 = fmaf(p2, R21, fmaf(p1, R11, p0 * R01)) * inv + br1;
        retr0 = (t > 0) ? nr0 : 0.f;
        retr1 = (t > 0) ? nr1 : 0.f;

        hrow[(size_t)t * HID] = h_new;
        h_own = h_new;
        gx0 = ngx0; gx1 = ngx1; gx2 = ngx2;
    }
}

// ============================================================================
// Phase 3: outputs = hiddens @ W_out.T + b_out   ([1M x 32] @ [32 x 16])
// 256 threads/block, 128 rows/block, grid 8192.
// ============================================================================
__global__ __launch_bounds__(256) void phase3_kernel(
    const float* __restrict__ hid,
    const float* __restrict__ W_out,
    const float* __restrict__ b_out,
    float* __restrict__ out)
{
    __shared__ __align__(16) float hs[128 * 34];
    __shared__ ull ws[16][16];
    __shared__ float bo[16];
    const int tid = threadIdx.x;

    {   // W_out pairs
        int o = tid >> 4, k = tid & 15;
        ws[o][k] = pack2(W_out[o * 32 + 2 * k], W_out[o * 32 + 2 * k + 1]);
    }
    if (tid < 16) bo[tid] = b_out[tid];

    const size_t base = (size_t)blockIdx.x * 128;
    const float* hp = hid + base * 32;
    for (int idx = tid; idx < 128 * 32; idx += 256) {
        int r = idx >> 5, c = idx & 31;
        hs[r * 34 + c] = hp[idx];
    }
    __syncthreads();

    const int row = tid >> 1, ob = (tid & 1) * 8;
    const ull* hr = (const ull*)(hs + row * 34);
    ull acc[8];
#pragma unroll
    for (int u = 0; u < 8; ++u) acc[u] = 0;
#pragma unroll
    for (int k = 0; k < 16; ++k) {
        ull hv = hr[k];
#pragma unroll
        for (int u = 0; u < 8; ++u) ffma2(acc[u], hv, ws[ob + u][k]);
    }
    float4 o0, o1;
    o0.x = hsum(acc[0]) + bo[ob];     o0.y = hsum(acc[1]) + bo[ob + 1];
    o0.z = hsum(acc[2]) + bo[ob + 2]; o0.w = hsum(acc[3]) + bo[ob + 3];
    o1.x = hsum(acc[4]) + bo[ob + 4]; o1.y = hsum(acc[5]) + bo[ob + 5];
    o1.z = hsum(acc[6]) + bo[ob + 6]; o1.w = hsum(acc[7]) + bo[ob + 7];
    float4* op = (float4*)(out + (base + row) * 16 + ob);
    op[0] = o0; op[1] = o1;
}

// ============================================================================
extern "C" void kernel_launch(void* const* d_in, const int* in_sizes, int n_in,
                              void* d_out, int out_size) {
    const float* inputs   = (const float*)d_in[0];
    const float* w_ih     = (const float*)d_in[1];
    const float* w_hh     = (const float*)d_in[2];
    const float* b_ih     = (const float*)d_in[3];
    const float* b_hh     = (const float*)d_in[4];
    const float* W_key    = (const float*)d_in[5];
    const float* b_key    = (const float*)d_in[6];
    const float* W_query  = (const float*)d_in[7];
    const float* b_query  = (const float*)d_in[8];
    const float* W_value  = (const float*)d_in[9];
    const float* b_value  = (const float*)d_in[10];
    const float* W_recall = (const float*)d_in[11];
    const float* b_recall = (const float*)d_in[12];
    const float* W_out    = (const float*)d_in[13];
    const float* b_out    = (const float*)d_in[14];

    float* out = (float*)d_out;                              // (B,S,16)
    float* hid = (float*)d_out + (size_t)BB * SS * 16;       // (B,S,32)

    precompute_kernel<<<1, 1024>>>(W_key, b_key, W_query, b_query,
                                   W_value, b_value, W_recall);
    phase1_kernel<<<4096, 128>>>(inputs, w_ih, b_ih);
    phase2_kernel<<<1024, 64>>>(w_ih, w_hh, b_hh, b_recall, hid);
    phase3_kernel<<<8192, 256>>>(hid, W_out, b_out, out);
}

// round 4
// speedup vs baseline: 1.0033x; 1.0033x over previous
#include <cuda_runtime.h>
#include <cstdint>

typedef unsigned long long ull;

#define BB 2048
#define SS 512
#define NROW (BB * SS)
#define G3 96
#define HID 32
#define INSZ 64

// -------- device scratch --------
__device__ float g_gx[(size_t)NROW * G3];   // precomputed input-part gates (+b_ih)
__device__ ull   g_Gp[16 * 32];             // packed pairs of G[i][j] = sum_k Wkey[k][i]*Wq[k][j]
__device__ float g_d[32];                   // d[j] = sum_k b_key[k]*Wq[k][j]
__device__ float g_gv[32];                  // g[i] = sum_k Wkey[k][i]*b_query[k]
__device__ float g_f[1];                    // f = b_key . b_query
__device__ float g_H[32 * 2];               // H[i][r] = sum_v Wval[v][i]*Wrec[r][v]
__device__ float g_e[2];                    // e[r] = sum_v b_value[v]*Wrec[r][v]

// -------- helpers --------
__device__ __forceinline__ void ffma2(ull& d, ull a, ull b) {
    asm("fma.rn.f32x2 %0, %1, %2, %0;" : "+l"(d) : "l"(a), "l"(b));
}
__device__ __forceinline__ ull pack2(float a, float b) {
    ull r; asm("mov.b64 %0, {%1, %2};" : "=l"(r) : "f"(a), "f"(b)); return r;
}
__device__ __forceinline__ float hsum(ull v) {
    return __uint_as_float((unsigned)v) + __uint_as_float((unsigned)(v >> 32));
}
// warp reduction: 5-deep shfl butterfly (no fp32 redux on sm_103)
__device__ __forceinline__ float wsum(float v) {
#pragma unroll
    for (int o = 16; o; o >>= 1) v += __shfl_xor_sync(0xffffffffu, v, o);
    return v;
}
__device__ __forceinline__ float sigmoidf_(float x) {
    return __fdividef(1.f, 1.f + __expf(-x));
}
__device__ __forceinline__ float tanhf_(float x) {
    return 1.f - __fdividef(2.f, __expf(2.f * x) + 1.f);
}

// ============================================================================
// Phase 0: precompute folded memory matrices
// ============================================================================
__global__ void precompute_kernel(
    const float* __restrict__ Wk, const float* __restrict__ bk,
    const float* __restrict__ Wq, const float* __restrict__ bq,
    const float* __restrict__ Wv, const float* __restrict__ bv,
    const float* __restrict__ Wr)
{
    __shared__ float Gs[32 * 32];
    int tid = threadIdx.x;
    {   // G[i][j]
        int i = tid >> 5, j = tid & 31;
        float s = 0.f;
        for (int k = 0; k < 64; ++k) s += Wk[k * 32 + i] * Wq[k * 32 + j];
        Gs[i * 32 + j] = s;
    }
    if (tid < 32) {
        float dv = 0.f, gv = 0.f;
        for (int k = 0; k < 64; ++k) {
            dv += bk[k] * Wq[k * 32 + tid];
            gv += Wk[k * 32 + tid] * bq[k];
        }
        g_d[tid] = dv; g_gv[tid] = gv;
    }
    if (tid == 0) {
        float f = 0.f;
        for (int k = 0; k < 64; ++k) f += bk[k] * bq[k];
        g_f[0] = f;
    }
    if (tid < 64) {
        int i = tid >> 1, r = tid & 1;
        float s = 0.f;
        for (int v = 0; v < 64; ++v) s += Wv[v * 32 + i] * Wr[r * 64 + v];
        g_H[i * 2 + r] = s;
    }
    if (tid < 2) {
        float s = 0.f;
        for (int v = 0; v < 64; ++v) s += bv[v] * Wr[tid * 64 + v];
        g_e[tid] = s;
    }
    __syncthreads();
    if (tid < 512) {
        int k = tid >> 5, j = tid & 31;
        g_Gp[tid] = pack2(Gs[(2 * k) * 32 + j], Gs[(2 * k + 1) * 32 + j]);
    }
}

// ============================================================================
// Phase 1: GX[row][96] = inputs[row][0:64] @ w_ih[:, :64].T + b_ih
// ============================================================================
__global__ __launch_bounds__(128) void phase1_kernel(
    const float* __restrict__ xin,
    const float* __restrict__ w_ih,
    const float* __restrict__ b_ih)
{
    __shared__ __align__(16) ulonglong2 w4s[16 * 96];
    __shared__ __align__(16) ulonglong2 xb[4][128];

    const int tid = threadIdx.x;
    const int w = tid >> 5, lane = tid & 31;

    for (int idx = tid; idx < 16 * 96; idx += 128) {
        int kq = idx / 96, j = idx % 96;
        const float* p = w_ih + j * 66 + kq * 4;
        ulonglong2 v; v.x = pack2(p[0], p[1]); v.y = pack2(p[2], p[3]);
        w4s[idx] = v;
    }
    const float b0 = b_ih[lane], b1 = b_ih[lane + 32], b2 = b_ih[lane + 64];
    __syncthreads();

    const int blockRow0 = blockIdx.x * 256;
    for (int tile = 0; tile < 8; ++tile) {
        const int rowBase = blockRow0 + tile * 32 + w * 8;
        const ulonglong2* src = (const ulonglong2*)(xin + (size_t)rowBase * INSZ);
        __syncwarp();
#pragma unroll
        for (int i = 0; i < 4; ++i) xb[w][lane + 32 * i] = src[lane + 32 * i];
        __syncwarp();

        ull acc[8][3];
#pragma unroll
        for (int r = 0; r < 8; ++r) { acc[r][0] = 0; acc[r][1] = 0; acc[r][2] = 0; }

#pragma unroll
        for (int kq = 0; kq < 16; ++kq) {
            ulonglong2 w0 = w4s[kq * 96 + lane];
            ulonglong2 w1 = w4s[kq * 96 + lane + 32];
            ulonglong2 w2 = w4s[kq * 96 + lane + 64];
#pragma unroll
            for (int r = 0; r < 8; ++r) {
                ulonglong2 xv = xb[w][r * 16 + kq];
                ffma2(acc[r][0], xv.x, w0.x); ffma2(acc[r][0], xv.y, w0.y);
                ffma2(acc[r][1], xv.x, w1.x); ffma2(acc[r][1], xv.y, w1.y);
                ffma2(acc[r][2], xv.x, w2.x); ffma2(acc[r][2], xv.y, w2.y);
            }
        }
#pragma unroll
        for (int r = 0; r < 8; ++r) {
            float* o = g_gx + (size_t)(rowBase + r) * G3;
            o[lane]      = hsum(acc[r][0]) + b0;
            o[lane + 32] = hsum(acc[r][1]) + b1;
            o[lane + 64] = hsum(acc[r][2]) + b2;
        }
    }
}

// ============================================================================
// Phase 2: sequential scan. One warp per batch element, lane = hidden index.
// Register diet: whh2 (n-gate) in smem, write-phase constants prologue-scoped.
// ============================================================================
__global__ __launch_bounds__(64, 7) void phase2_kernel(
    const float* __restrict__ w_ih,
    const float* __restrict__ w_hh,
    const float* __restrict__ b_hh,
    const float* __restrict__ b_recall,
    float* __restrict__ hid)
{
    __shared__ __align__(16) float hbuf[2][32];
    __shared__ __align__(16) ull whh2s[16][33];   // padded: per-lane LDS.64 deg-2

    const int tid = threadIdx.x;
    const int w = tid >> 5, lane = tid & 31;
    const int b = blockIdx.x * 2 + w;

    // n-gate weights -> shared (block-common)
    for (int idx = tid; idx < 512; idx += 64) {
        int k = idx >> 5, l = idx & 31;
        whh2s[k][l] = pack2(w_hh[(l + 64) * 32 + 2 * k],
                            w_hh[(l + 64) * 32 + 2 * k + 1]);
    }

    ull whh0[16], whh1[16];
    {
        const ulonglong2* p0 = (const ulonglong2*)(w_hh + (size_t)lane * 32);
        const ulonglong2* p1 = (const ulonglong2*)(w_hh + (size_t)(lane + 32) * 32);
#pragma unroll
        for (int i = 0; i < 8; ++i) {
            ulonglong2 v;
            v = p0[i]; whh0[2 * i] = v.x; whh0[2 * i + 1] = v.y;
            v = p1[i]; whh1[2 * i] = v.x; whh1[2 * i + 1] = v.y;
        }
    }
    __syncthreads();

    const float wr00 = w_ih[lane * 66 + 64],        wr01 = w_ih[lane * 66 + 65];
    const float wr10 = w_ih[(lane + 32) * 66 + 64], wr11 = w_ih[(lane + 32) * 66 + 65];
    const float wr20 = w_ih[(lane + 64) * 66 + 64], wr21 = w_ih[(lane + 64) * 66 + 65];
    const float bh0 = b_hh[lane], bh1 = b_hh[lane + 32], bh2 = b_hh[lane + 64];
    const float br0 = b_recall[0], br1 = b_recall[1];

    float A0o = 0.f, A1o = 0.f, A2o = 0.f;
    float c0 = 0.f, c1 = 0.f, c2 = 0.f;
    float R00 = 0.f, R01 = 0.f, R10 = 0.f, R11 = 0.f, R20 = 0.f, R21 = 0.f;
    float retr0 = 0.f, retr1 = 0.f, h_own = 0.f;

    const float* gxp = g_gx + (size_t)b * SS * G3;
    float* hrow = hid + (size_t)b * SS * HID + lane;
    float gx0 = gxp[lane], gx1 = gxp[lane + 32], gx2 = gxp[lane + 64];
    ull* hbU = (ull*)hbuf[w];

    // ---------- prologue: t = 0..3 (memory writes + flush + masked softmax) ----------
    {
        const float dj = g_d[lane], g_own = g_gv[lane];
        const float H0o = g_H[lane * 2], H1o = g_H[lane * 2 + 1];
        const float fv = g_f[0], e0c = g_e[0], e1c = g_e[1];
#pragma unroll
        for (int t = 0; t < 4; ++t) {
            float gxr = fmaf(retr1, wr01, fmaf(retr0, wr00, gx0));
            float gxz = fmaf(retr1, wr11, fmaf(retr0, wr10, gx1));
            float gxn = fmaf(retr1, wr21, fmaf(retr0, wr20, gx2));
            const float* q = gxp + (size_t)(t + 1) * G3;
            gx0 = q[lane]; gx1 = q[lane + 32]; gx2 = q[lane + 64];

            hbuf[w][lane] = h_own; __syncwarp();
            ull ar = 0, az = 0, an = 0;
#pragma unroll
            for (int k = 0; k < 16; ++k) {
                ull hp = hbU[k];
                ffma2(ar, hp, whh0[k]);
                ffma2(az, hp, whh1[k]);
                ffma2(an, hp, whh2s[k][lane]);
            }
            __syncwarp();
            float ghr = hsum(ar) + bh0, ghz = hsum(az) + bh1, ghn = hsum(an) + bh2;
            float r = sigmoidf_(gxr + ghr);
            float z = sigmoidf_(gxz + ghz);
            float n = tanhf_(fmaf(r, ghn, gxn));
            float h_new = (t == 3) ? 0.f : fmaf(z, h_own - n, n);

            if (t < 3) {   // fold this step's memory write into A/c/R
                hbuf[w][lane] = h_new; __syncwarp();
                ull aa = 0;
#pragma unroll
                for (int k = 0; k < 16; ++k) ffma2(aa, hbU[k], g_Gp[k * 32 + lane]);
                __syncwarp();
                float Av  = hsum(aa) + dj;
                float cv  = wsum(h_new * g_own) + fv;
                float Rv0 = wsum(h_new * H0o) + e0c;
                float Rv1 = wsum(h_new * H1o) + e1c;
                if (t == 0)      { A0o = Av; c0 = cv; R00 = Rv0; R01 = Rv1; }
                else if (t == 1) { A1o = Av; c1 = cv; R10 = Rv0; R11 = Rv1; }
                else             { A2o = Av; c2 = cv; R20 = Rv0; R21 = Rv1; }
            }
            // masked attention read (counter = t, capped at 3)
            float s0 = wsum(h_new * A0o) + c0;
            float s1 = wsum(h_new * A1o) + c1;
            float s2 = wsum(h_new * A2o) + c2;
            int counter = (t < 3) ? t : 3;
            float m0 = (0 < counter) ? s0 : -1e30f;
            float m1 = (1 < counter) ? s1 : -1e30f;
            float m2 = (2 < counter) ? s2 : -1e30f;
            float p0 = __expf(m0), p1 = __expf(m1), p2 = __expf(m2);
            float inv = __fdividef(1.f, p0 + p1 + p2);
            float nr0 = fmaf(p2, R20, fmaf(p1, R10, p0 * R00)) * inv + br0;
            float nr1 = fmaf(p2, R21, fmaf(p1, R11, p0 * R01)) * inv + br1;
            retr0 = (t > 0) ? nr0 : 0.f;
            retr1 = (t > 0) ? nr1 : 0.f;
            hrow[(size_t)t * HID] = h_new;
            h_own = h_new;
        }
    }

    // ---------- hot loop: t = 4..511 (no branches, no masks) ----------
    for (int t = 4; t < SS; ++t) {
        float gxr = fmaf(retr1, wr01, fmaf(retr0, wr00, gx0));
        float gxz = fmaf(retr1, wr11, fmaf(retr0, wr10, gx1));
        float gxn = fmaf(retr1, wr21, fmaf(retr0, wr20, gx2));
        const float* q = gxp + (size_t)((t + 1 < SS) ? t + 1 : t) * G3;
        gx0 = q[lane]; gx1 = q[lane + 32]; gx2 = q[lane + 64];

        hbuf[w][lane] = h_own; __syncwarp();
        ull ar = 0, az = 0, an = 0;
#pragma unroll
        for (int k = 0; k < 16; ++k) {
            ull hp = hbU[k];
            ffma2(ar, hp, whh0[k]);
            ffma2(az, hp, whh1[k]);
            ffma2(an, hp, whh2s[k][lane]);
        }
        __syncwarp();
        float ghr = hsum(ar) + bh0, ghz = hsum(az) + bh1, ghn = hsum(an) + bh2;
        float r = sigmoidf_(gxr + ghr);
        float z = sigmoidf_(gxz + ghz);
        float n = tanhf_(fmaf(r, ghn, gxn));
        float h_new = fmaf(z, h_own - n, n);

        float s0 = wsum(h_new * A0o) + c0;
        float s1 = wsum(h_new * A1o) + c1;
        float s2 = wsum(h_new * A2o) + c2;
        float p0 = __expf(s0), p1 = __expf(s1), p2 = __expf(s2);
        float inv = __fdividef(1.f, p0 + p1 + p2);
        retr0 = fmaf(p2, R20, fmaf(p1, R10, p0 * R00)) * inv + br0;
        retr1 = fmaf(p2, R21, fmaf(p1, R11, p0 * R01)) * inv + br1;

        hrow[(size_t)t * HID] = h_new;
        h_own = h_new;
    }
}

// ============================================================================
// Phase 3: outputs = hiddens @ W_out.T + b_out. Row-per-thread streaming.
// ============================================================================
__global__ __launch_bounds__(256) void phase3_kernel(
    const float* __restrict__ hid,
    const float* __restrict__ W_out,
    const float* __restrict__ b_out,
    float* __restrict__ out)
{
    __shared__ ull ws[16][16];
    __shared__ float bo[16];
    const int tid = threadIdx.x;
    {
        int o = tid >> 4, k = tid & 15;
        ws[o][k] = pack2(W_out[o * 32 + 2 * k], W_out[o * 32 + 2 * k + 1]);
    }
    if (tid < 16) bo[tid] = b_out[tid];
    __syncthreads();

    const size_t row = (size_t)blockIdx.x * 256 + tid;
    const ulonglong2* hp = (const ulonglong2*)(hid + row * 32);
    ull h2[16];
#pragma unroll
    for (int i = 0; i < 8; ++i) {
        ulonglong2 v = hp[i];
        h2[2 * i] = v.x; h2[2 * i + 1] = v.y;
    }
    float ov[16];
#pragma unroll
    for (int j = 0; j < 16; ++j) {
        ull acc = 0;
#pragma unroll
        for (int k = 0; k < 16; ++k) ffma2(acc, h2[k], ws[j][k]);
        ov[j] = hsum(acc) + bo[j];
    }
    float4* op = (float4*)(out + row * 16);
#pragma unroll
    for (int i = 0; i < 4; ++i)
        op[i] = make_float4(ov[4 * i], ov[4 * i + 1], ov[4 * i + 2], ov[4 * i + 3]);
}

// ============================================================================
extern "C" void kernel_launch(void* const* d_in, const int* in_sizes, int n_in,
                              void* d_out, int out_size) {
    const float* inputs   = (const float*)d_in[0];
    const float* w_ih     = (const float*)d_in[1];
    const float* w_hh     = (const float*)d_in[2];
    const float* b_ih     = (const float*)d_in[3];
    const float* b_hh     = (const float*)d_in[4];
    const float* W_key    = (const float*)d_in[5];
    const float* b_key    = (const float*)d_in[6];
    const float* W_query  = (const float*)d_in[7];
    const float* b_query  = (const float*)d_in[8];
    const float* W_value  = (const float*)d_in[9];
    const float* b_value  = (const float*)d_in[10];
    const float* W_recall = (const float*)d_in[11];
    const float* b_recall = (const float*)d_in[12];
    const float* W_out    = (const float*)d_in[13];
    const float* b_out    = (const float*)d_in[14];

    float* out = (float*)d_out;                              // (B,S,16)
    float* hid = (float*)d_out + (size_t)BB * SS * 16;       // (B,S,32)

    precompute_kernel<<<1, 1024>>>(W_key, b_key, W_query, b_query,
                                   W_value, b_value, W_recall);
    phase1_kernel<<<4096, 128>>>(inputs, w_ih, b_ih);
    phase2_kernel<<<1024, 64>>>(w_ih, w_hh, b_hh, b_recall, hid);
    phase3_kernel<<<4096, 256>>>(hid, W_out, b_out, out);
}

// round 6
// speedup vs baseline: 1.4741x; 1.4693x over previous
#include <cuda_runtime.h>
#include <cstdint>

typedef unsigned long long ull;

#define BB 2048
#define SS 512
#define NROW (BB * SS)
#define G3 96
#define HID 32
#define INSZ 64

// -------- device scratch --------
__device__ float g_gx[(size_t)NROW * G3];   // precomputed input-part gates (+b_ih)
__device__ ull   g_Gp[16 * 32];             // packed pairs of G[i][j] = sum_k Wkey[k][i]*Wq[k][j]
__device__ float g_d[32];
__device__ float g_gv[32];
__device__ float g_f[1];
__device__ float g_H[32 * 2];
__device__ float g_e[2];

// -------- helpers --------
__device__ __forceinline__ void ffma2(ull& d, ull a, ull b) {
    asm("fma.rn.f32x2 %0, %1, %2, %0;" : "+l"(d) : "l"(a), "l"(b));
}
__device__ __forceinline__ ull pack2(float a, float b) {
    ull r; asm("mov.b64 %0, {%1, %2};" : "=l"(r) : "f"(a), "f"(b)); return r;
}
__device__ __forceinline__ float hsum(ull v) {
    return __uint_as_float((unsigned)v) + __uint_as_float((unsigned)(v >> 32));
}
__device__ __forceinline__ float wsum(float v) {
#pragma unroll
    for (int o = 16; o; o >>= 1) v += __shfl_xor_sync(0xffffffffu, v, o);
    return v;
}
__device__ __forceinline__ float sigmoidf_(float x) {
    return __fdividef(1.f, 1.f + __expf(-x));
}
__device__ __forceinline__ float tanhf_(float x) {
    return 1.f - __fdividef(2.f, __expf(2.f * x) + 1.f);
}

// ============================================================================
// Phase 0: precompute folded memory matrices
// ============================================================================
__global__ void precompute_kernel(
    const float* __restrict__ Wk, const float* __restrict__ bk,
    const float* __restrict__ Wq, const float* __restrict__ bq,
    const float* __restrict__ Wv, const float* __restrict__ bv,
    const float* __restrict__ Wr)
{
    __shared__ float Gs[32 * 32];
    int tid = threadIdx.x;
    {
        int i = tid >> 5, j = tid & 31;
        float s = 0.f;
        for (int k = 0; k < 64; ++k) s += Wk[k * 32 + i] * Wq[k * 32 + j];
        Gs[i * 32 + j] = s;
    }
    if (tid < 32) {
        float dv = 0.f, gv = 0.f;
        for (int k = 0; k < 64; ++k) {
            dv += bk[k] * Wq[k * 32 + tid];
            gv += Wk[k * 32 + tid] * bq[k];
        }
        g_d[tid] = dv; g_gv[tid] = gv;
    }
    if (tid == 0) {
        float f = 0.f;
        for (int k = 0; k < 64; ++k) f += bk[k] * bq[k];
        g_f[0] = f;
    }
    if (tid < 64) {
        int i = tid >> 1, r = tid & 1;
        float s = 0.f;
        for (int v = 0; v < 64; ++v) s += Wv[v * 32 + i] * Wr[r * 64 + v];
        g_H[i * 2 + r] = s;
    }
    if (tid < 2) {
        float s = 0.f;
        for (int v = 0; v < 64; ++v) s += bv[v] * Wr[tid * 64 + v];
        g_e[tid] = s;
    }
    __syncthreads();
    if (tid < 512) {
        int k = tid >> 5, j = tid & 31;
        g_Gp[tid] = pack2(Gs[(2 * k) * 32 + j], Gs[(2 * k + 1) * 32 + j]);
    }
}

// ============================================================================
// Phase 1: GX[row][96] = inputs[row][0:64] @ w_ih[:, :64].T + b_ih
// ============================================================================
__global__ __launch_bounds__(128) void phase1_kernel(
    const float* __restrict__ xin,
    const float* __restrict__ w_ih,
    const float* __restrict__ b_ih)
{
    __shared__ __align__(16) ulonglong2 w4s[16 * 96];
    __shared__ __align__(16) ulonglong2 xb[4][128];

    const int tid = threadIdx.x;
    const int w = tid >> 5, lane = tid & 31;

    for (int idx = tid; idx < 16 * 96; idx += 128) {
        int kq = idx / 96, j = idx % 96;
        const float* p = w_ih + j * 66 + kq * 4;
        ulonglong2 v; v.x = pack2(p[0], p[1]); v.y = pack2(p[2], p[3]);
        w4s[idx] = v;
    }
    const float b0 = b_ih[lane], b1 = b_ih[lane + 32], b2 = b_ih[lane + 64];
    __syncthreads();

    const int blockRow0 = blockIdx.x * 256;
    for (int tile = 0; tile < 8; ++tile) {
        const int rowBase = blockRow0 + tile * 32 + w * 8;
        const ulonglong2* src = (const ulonglong2*)(xin + (size_t)rowBase * INSZ);
        __syncwarp();
#pragma unroll
        for (int i = 0; i < 4; ++i) xb[w][lane + 32 * i] = src[lane + 32 * i];
        __syncwarp();

        ull acc[8][3];
#pragma unroll
        for (int r = 0; r < 8; ++r) { acc[r][0] = 0; acc[r][1] = 0; acc[r][2] = 0; }

#pragma unroll
        for (int kq = 0; kq < 16; ++kq) {
            ulonglong2 w0 = w4s[kq * 96 + lane];
            ulonglong2 w1 = w4s[kq * 96 + lane + 32];
            ulonglong2 w2 = w4s[kq * 96 + lane + 64];
#pragma unroll
            for (int r = 0; r < 8; ++r) {
                ulonglong2 xv = xb[w][r * 16 + kq];
                ffma2(acc[r][0], xv.x, w0.x); ffma2(acc[r][0], xv.y, w0.y);
                ffma2(acc[r][1], xv.x, w1.x); ffma2(acc[r][1], xv.y, w1.y);
                ffma2(acc[r][2], xv.x, w2.x); ffma2(acc[r][2], xv.y, w2.y);
            }
        }
#pragma unroll
        for (int r = 0; r < 8; ++r) {
            float* o = g_gx + (size_t)(rowBase + r) * G3;
            o[lane]      = hsum(acc[r][0]) + b0;
            o[lane + 32] = hsum(acc[r][1]) + b1;
            o[lane + 64] = hsum(acc[r][2]) + b2;
        }
    }
}

// ============================================================================
// Phase 2: sequential scan. One warp per batch element, lane = hidden index.
// Unroll-2 hot loop, 2-deep gx prefetch, parity h-broadcast (1 syncwarp/step).
// ============================================================================
__global__ __launch_bounds__(64, 7) void phase2_kernel(
    const float* __restrict__ w_ih,
    const float* __restrict__ w_hh,
    const float* __restrict__ b_hh,
    const float* __restrict__ b_recall,
    float* __restrict__ hid)
{
    __shared__ __align__(16) float hbuf[2][3][32];   // [warp][slot][lane]
    __shared__ __align__(16) ull whh2s[16][33];      // n-gate weights, padded

    const int tid = threadIdx.x;
    const int w = tid >> 5, lane = tid & 31;
    const int b = blockIdx.x * 2 + w;

    for (int idx = tid; idx < 512; idx += 64) {
        int k = idx >> 5, l = idx & 31;
        whh2s[k][l] = pack2(w_hh[(l + 64) * 32 + 2 * k],
                            w_hh[(l + 64) * 32 + 2 * k + 1]);
    }

    ull whh0[16], whh1[16];
    {
        const ulonglong2* p0 = (const ulonglong2*)(w_hh + (size_t)lane * 32);
        const ulonglong2* p1 = (const ulonglong2*)(w_hh + (size_t)(lane + 32) * 32);
#pragma unroll
        for (int i = 0; i < 8; ++i) {
            ulonglong2 v;
            v = p0[i]; whh0[2 * i] = v.x; whh0[2 * i + 1] = v.y;
            v = p1[i]; whh1[2 * i] = v.x; whh1[2 * i + 1] = v.y;
        }
    }
    __syncthreads();

    const float wr00 = w_ih[lane * 66 + 64],        wr01 = w_ih[lane * 66 + 65];
    const float wr10 = w_ih[(lane + 32) * 66 + 64], wr11 = w_ih[(lane + 32) * 66 + 65];
    const float wr20 = w_ih[(lane + 64) * 66 + 64], wr21 = w_ih[(lane + 64) * 66 + 65];
    const float bh0 = b_hh[lane], bh1 = b_hh[lane + 32], bh2 = b_hh[lane + 64];
    const float br0 = b_recall[0], br1 = b_recall[1];

    float A0o = 0.f, A1o = 0.f, A2o = 0.f;
    float c0 = 0.f, c1 = 0.f, c2 = 0.f;
    float R00 = 0.f, R01 = 0.f, R10 = 0.f, R11 = 0.f, R20 = 0.f, R21 = 0.f;
    float retr0 = 0.f, retr1 = 0.f, h_own = 0.f;

    const float* gxp = g_gx + (size_t)b * SS * G3;
    float* hrow = hid + (size_t)b * SS * HID + lane;
    float gx0 = gxp[lane], gx1 = gxp[lane + 32], gx2 = gxp[lane + 64];
    ull* hb2 = (ull*)hbuf[w][2];

    // ---------- prologue: t = 0..3 ----------
    {
        const float dj = g_d[lane], g_own = g_gv[lane];
        const float H0o = g_H[lane * 2], H1o = g_H[lane * 2 + 1];
        const float fv = g_f[0], e0c = g_e[0], e1c = g_e[1];
#pragma unroll
        for (int t = 0; t < 4; ++t) {
            float gxr = fmaf(retr1, wr01, fmaf(retr0, wr00, gx0));
            float gxz = fmaf(retr1, wr11, fmaf(retr0, wr10, gx1));
            float gxn = fmaf(retr1, wr21, fmaf(retr0, wr20, gx2));
            const float* q = gxp + (size_t)(t + 1) * G3;
            gx0 = q[lane]; gx1 = q[lane + 32]; gx2 = q[lane + 64];

            hbuf[w][2][lane] = h_own; __syncwarp();
            ull ar = 0, az = 0, an = 0;
#pragma unroll
            for (int k = 0; k < 16; ++k) {
                ull hp = hb2[k];
                ffma2(ar, hp, whh0[k]);
                ffma2(az, hp, whh1[k]);
                ffma2(an, hp, whh2s[k][lane]);
            }
            __syncwarp();
            float ghr = hsum(ar) + bh0, ghz = hsum(az) + bh1, ghn = hsum(an) + bh2;
            float r = sigmoidf_(gxr + ghr);
            float z = sigmoidf_(gxz + ghz);
            float n = tanhf_(fmaf(r, ghn, gxn));
            float h_new = (t == 3) ? 0.f : fmaf(z, h_own - n, n);

            if (t < 3) {
                hbuf[w][2][lane] = h_new; __syncwarp();
                ull aa = 0;
#pragma unroll
                for (int k = 0; k < 16; ++k) ffma2(aa, hb2[k], g_Gp[k * 32 + lane]);
                __syncwarp();
                float Av  = hsum(aa) + dj;
                float cv  = wsum(h_new * g_own) + fv;
                float Rv0 = wsum(h_new * H0o) + e0c;
                float Rv1 = wsum(h_new * H1o) + e1c;
                if (t == 0)      { A0o = Av; c0 = cv; R00 = Rv0; R01 = Rv1; }
                else if (t == 1) { A1o = Av; c1 = cv; R10 = Rv0; R11 = Rv1; }
                else             { A2o = Av; c2 = cv; R20 = Rv0; R21 = Rv1; }
            }
            float s0 = wsum(h_new * A0o) + c0;
            float s1 = wsum(h_new * A1o) + c1;
            float s2 = wsum(h_new * A2o) + c2;
            int counter = (t < 3) ? t : 3;
            float m0 = (0 < counter) ? s0 : -1e30f;
            float m1 = (1 < counter) ? s1 : -1e30f;
            float m2 = (2 < counter) ? s2 : -1e30f;
            float p0 = __expf(m0), p1 = __expf(m1), p2 = __expf(m2);
            float inv = __fdividef(1.f, p0 + p1 + p2);
            float nr0 = fmaf(p2, R20, fmaf(p1, R10, p0 * R00)) * inv + br0;
            float nr1 = fmaf(p2, R21, fmaf(p1, R11, p0 * R01)) * inv + br1;
            retr0 = (t > 0) ? nr0 : 0.f;
            retr1 = (t > 0) ? nr1 : 0.f;
            hrow[(size_t)t * HID] = h_new;
            h_own = h_new;
        }
    }

    // gxA = gx(4) (already in gx0..2); load gxB = gx(5)
    float gA0 = gx0, gA1 = gx1, gA2 = gx2;
    const float* q5 = gxp + (size_t)5 * G3;
    float gB0 = q5[lane], gB1 = q5[lane + 32], gB2 = q5[lane + 64];

    ull* hbP0 = (ull*)hbuf[w][0];
    ull* hbP1 = (ull*)hbuf[w][1];

    // ---------- hot loop: t = 4..511, unrolled by 2, 2-deep prefetch ----------
#define STEP(PBUF, PARR, GX0, GX1, GX2, TPRE)                                   \
    {                                                                           \
        const float* q = gxp + (size_t)((TPRE) < SS ? (TPRE) : SS - 1) * G3;    \
        float n0 = q[lane], n1 = q[lane + 32], n2 = q[lane + 64];               \
        float gxr = fmaf(retr1, wr01, fmaf(retr0, wr00, GX0));                  \
        float gxz = fmaf(retr1, wr11, fmaf(retr0, wr10, GX1));                  \
        float gxn = fmaf(retr1, wr21, fmaf(retr0, wr20, GX2));                  \
        PBUF[lane] = h_own; __syncwarp();                                       \
        ull ar = 0, az = 0, an = 0;                                             \
        _Pragma("unroll")                                                       \
        for (int k = 0; k < 16; ++k) {                                          \
            ull hp = PARR[k];                                                   \
            ffma2(ar, hp, whh0[k]);                                             \
            ffma2(az, hp, whh1[k]);                                             \
            ffma2(an, hp, whh2s[k][lane]);                                      \
        }                                                                       \
        float ghr = hsum(ar) + bh0, ghz = hsum(az) + bh1, ghn = hsum(an) + bh2; \
        float r = sigmoidf_(gxr + ghr);                                         \
        float z = sigmoidf_(gxz + ghz);                                         \
        float n = tanhf_(fmaf(r, ghn, gxn));                                    \
        float h_new = fmaf(z, h_own - n, n);                                    \
        hrow[(size_t)t_cur * HID] = h_new;                                      \
        float s0 = wsum(h_new * A0o) + c0;                                      \
        float s1 = wsum(h_new * A1o) + c1;                                      \
        float s2 = wsum(h_new * A2o) + c2;                                      \
        float p0 = __expf(s0), p1 = __expf(s1), p2 = __expf(s2);                \
        float inv = __fdividef(1.f, p0 + p1 + p2);                              \
        retr0 = fmaf(p2, R20, fmaf(p1, R10, p0 * R00)) * inv + br0;             \
        retr1 = fmaf(p2, R21, fmaf(p1, R11, p0 * R01)) * inv + br1;             \
        h_own = h_new;                                                          \
        GX0 = n0; GX1 = n1; GX2 = n2;                                           \
    }

    for (int t = 4; t < SS; t += 2) {
        {   // step t (parity 0), prefetch t+2
            int t_cur = t;
            STEP((&hbuf[w][0][0]), hbP0, gA0, gA1, gA2, t + 2)
        }
        {   // step t+1 (parity 1), prefetch t+3
            int t_cur = t + 1;
            STEP((&hbuf[w][1][0]), hbP1, gB0, gB1, gB2, t + 3)
        }
    }
#undef STEP
}

// ============================================================================
// Phase 3: outputs = hiddens @ W_out.T + b_out.
// Warp = 2 rows x 16 outputs; W_out rows in registers; h staged in padded smem.
// ============================================================================
__global__ __launch_bounds__(256) void phase3_kernel(
    const float* __restrict__ hid,
    const float* __restrict__ W_out,
    const float* __restrict__ b_out,
    float* __restrict__ out)
{
    __shared__ __align__(16) float hs[256 * 36];    // 256 rows, stride 36 (36 KB)

    const int tid = threadIdx.x;
    const int w = tid >> 5, lane = tid & 31;
    const int j = lane & 15;                         // output index
    const int half = lane >> 4;                      // 0: even row, 1: odd row

    // W_out row j -> 16 packed-pair registers; bias
    ull wreg[16];
#pragma unroll
    for (int k = 0; k < 16; ++k)
        wreg[k] = pack2(W_out[j * 32 + 2 * k], W_out[j * 32 + 2 * k + 1]);
    const float bj = b_out[j];

    // stage 256 rows coalesced -> padded smem
    const size_t base = (size_t)blockIdx.x * 256;
    const float4* src = (const float4*)(hid + base * 32);
    for (int idx = tid; idx < 2048; idx += 256) {    // 2048 float4
        float4 v = src[idx];
        int r = idx >> 3, c4 = (idx & 7) * 4;
        float* d = hs + r * 36 + c4;
        d[0] = v.x; d[1] = v.y; d[2] = v.z; d[3] = v.w;
    }
    __syncthreads();

    // each warp: 32 rows = 16 pair-iterations
    const int row0 = w * 32;
#pragma unroll 4
    for (int i = 0; i < 16; ++i) {
        const int r = row0 + 2 * i + half;
        const ull* hr = (const ull*)(hs + r * 36);
        ull acc = 0;
#pragma unroll
        for (int k = 0; k < 16; ++k) ffma2(acc, hr[k], wreg[k]);
        out[(base + r) * 16 + j] = hsum(acc) + bj;
    }
}

// ============================================================================
extern "C" void kernel_launch(void* const* d_in, const int* in_sizes, int n_in,
                              void* d_out, int out_size) {
    const float* inputs   = (const float*)d_in[0];
    const float* w_ih     = (const float*)d_in[1];
    const float* w_hh     = (const float*)d_in[2];
    const float* b_ih     = (const float*)d_in[3];
    const float* b_hh     = (const float*)d_in[4];
    const float* W_key    = (const float*)d_in[5];
    const float* b_key    = (const float*)d_in[6];
    const float* W_query  = (const float*)d_in[7];
    const float* b_query  = (const float*)d_in[8];
    const float* W_value  = (const float*)d_in[9];
    const float* b_value  = (const float*)d_in[10];
    const float* W_recall = (const float*)d_in[11];
    const float* b_recall = (const float*)d_in[12];
    const float* W_out    = (const float*)d_in[13];
    const float* b_out    = (const float*)d_in[14];

    float* out = (float*)d_out;                              // (B,S,16)
    float* hid = (float*)d_out + (size_t)BB * SS * 16;       // (B,S,32)

    precompute_kernel<<<1, 1024>>>(W_key, b_key, W_query, b_query,
                                   W_value, b_value, W_recall);
    phase1_kernel<<<4096, 128>>>(inputs, w_ih, b_ih);
    phase2_kernel<<<1024, 64>>>(w_ih, w_hh, b_hh, b_recall, hid);
    phase3_kernel<<<4096, 256>>>(hid, W_out, b_out, out);
}